// round 1
// baseline (speedup 1.0000x reference)
#include <cuda_runtime.h>
#include <math.h>

// Scratch (allocation-free): QKV activations and attention output.
__device__ float g_qkv[(size_t)4096 * 3072];  // [B*S][3*EMBD]
__device__ float g_att[(size_t)4096 * 1024];  // [B*S][EMBD]

#define BM 128
#define BN 128
#define BK 16

// C[m,n] = sum_k A[m,k] * B[n,k] + bias[n]
// A: [M,K] row-major, B: [N,K] row-major (torch-style weight), both K-contiguous.
__global__ __launch_bounds__(256) void gemm_tn_bias(
    const float* __restrict__ A, const float* __restrict__ Bw,
    const float* __restrict__ bias, float* __restrict__ C,
    int M, int N, int K)
{
    __shared__ float As[BK][BM + 4];
    __shared__ float Bs[BK][BN + 4];

    int tid = threadIdx.x;
    int bm = blockIdx.y * BM;
    int bn = blockIdx.x * BN;
    int ty = tid >> 4;   // 0..15
    int tx = tid & 15;   // 0..15

    float acc[8][8];
#pragma unroll
    for (int i = 0; i < 8; i++)
#pragma unroll
        for (int j = 0; j < 8; j++) acc[i][j] = 0.f;

    for (int k0 = 0; k0 < K; k0 += BK) {
        // Load 128x16 tiles of A and B, transposed into [k][m] layout.
#pragma unroll
        for (int r = 0; r < 2; r++) {
            int idx = r * 256 + tid;       // 0..511 float4 slots
            int row = idx >> 2;            // 0..127
            int col = (idx & 3) * 4;       // 0,4,8,12
            float4 va = *(const float4*)&A[(size_t)(bm + row) * K + k0 + col];
            As[col + 0][row] = va.x; As[col + 1][row] = va.y;
            As[col + 2][row] = va.z; As[col + 3][row] = va.w;
            float4 vb = *(const float4*)&Bw[(size_t)(bn + row) * K + k0 + col];
            Bs[col + 0][row] = vb.x; Bs[col + 1][row] = vb.y;
            Bs[col + 2][row] = vb.z; Bs[col + 3][row] = vb.w;
        }
        __syncthreads();

#pragma unroll
        for (int k = 0; k < BK; k++) {
            float4 a0 = *(const float4*)&As[k][ty * 8];
            float4 a1 = *(const float4*)&As[k][ty * 8 + 4];
            float4 b0 = *(const float4*)&Bs[k][tx * 8];
            float4 b1 = *(const float4*)&Bs[k][tx * 8 + 4];
            float a[8] = {a0.x, a0.y, a0.z, a0.w, a1.x, a1.y, a1.z, a1.w};
            float b[8] = {b0.x, b0.y, b0.z, b0.w, b1.x, b1.y, b1.z, b1.w};
#pragma unroll
            for (int i = 0; i < 8; i++)
#pragma unroll
                for (int j = 0; j < 8; j++)
                    acc[i][j] = fmaf(a[i], b[j], acc[i][j]);
        }
        __syncthreads();
    }

#pragma unroll
    for (int i = 0; i < 8; i++) {
        size_t row = bm + ty * 8 + i;
#pragma unroll
        for (int j = 0; j < 8; j++) {
            int cn = bn + tx * 8 + j;
            C[row * N + cn] = acc[i][j] + bias[cn];
        }
    }
}

// Flash attention, fp32. Block: 64 queries of one (b,h). 256 threads.
// qkv layout: [4096][3072]; q at col h*64, k at 1024+h*64, v at 2048+h*64.
__global__ __launch_bounds__(256) void attn_kernel(
    const float* __restrict__ qkv, float* __restrict__ out)
{
    __shared__ float Qt[64][68];   // [d][q], scale folded in
    __shared__ float Kt[64][33];   // [d][k]
    __shared__ float Vs[32][68];   // [k][d]
    __shared__ float Ss[64][36];   // [q][k] scores -> probs
    __shared__ float m_s[64], l_s[64], corr_s[64];

    int tid = threadIdx.x;
    int bh = blockIdx.y;
    int b = bh >> 4, h = bh & 15;
    int qbase = blockIdx.x * 64;
    const float* base = qkv + (size_t)b * 2048 * 3072 + h * 64;
    const float scale = 0.125f;  // 1/sqrt(64)

    // Load Q tile transposed, fold softmax scale.
#pragma unroll
    for (int i = 0; i < 4; i++) {
        int idx = i * 256 + tid;     // 1024 float4 slots
        int q = idx >> 4;            // 0..63
        int d4 = (idx & 15) * 4;     // 0..60
        float4 v = *(const float4*)&base[(size_t)(qbase + q) * 3072 + d4];
        Qt[d4 + 0][q] = v.x * scale; Qt[d4 + 1][q] = v.y * scale;
        Qt[d4 + 2][q] = v.z * scale; Qt[d4 + 3][q] = v.w * scale;
    }
    if (tid < 64) { m_s[tid] = -INFINITY; l_s[tid] = 0.f; }

    int ty = tid >> 4, tx = tid & 15;
    int q0 = ty * 4;
    float accO[4][4];
#pragma unroll
    for (int i = 0; i < 4; i++)
#pragma unroll
        for (int j = 0; j < 4; j++) accO[i][j] = 0.f;

    for (int kt = 0; kt < 2048; kt += 32) {
        __syncthreads();  // protect Kt/Vs/Ss from previous iteration readers
        // Load K (transposed) and V tiles: 32 rows x 64 cols each.
#pragma unroll
        for (int i = 0; i < 2; i++) {
            int idx = i * 256 + tid;   // 512 float4 slots
            int r = idx >> 4;          // 0..31
            int d4 = (idx & 15) * 4;
            const float* rp = &base[(size_t)(kt + r) * 3072 + d4];
            float4 kv = *(const float4*)(rp + 1024);
            Kt[d4 + 0][r] = kv.x; Kt[d4 + 1][r] = kv.y;
            Kt[d4 + 2][r] = kv.z; Kt[d4 + 3][r] = kv.w;
            float4 vv = *(const float4*)(rp + 2048);
            *(float4*)&Vs[r][d4] = vv;
        }
        __syncthreads();

        // Scores: micro 4q x 2k per thread.
        int k0 = tx * 2;
        float s00 = 0, s01 = 0, s10 = 0, s11 = 0, s20 = 0, s21 = 0, s30 = 0, s31 = 0;
#pragma unroll
        for (int dd = 0; dd < 64; dd++) {
            float4 qv = *(const float4*)&Qt[dd][q0];
            float ka = Kt[dd][k0], kb = Kt[dd][k0 + 1];
            s00 = fmaf(qv.x, ka, s00); s01 = fmaf(qv.x, kb, s01);
            s10 = fmaf(qv.y, ka, s10); s11 = fmaf(qv.y, kb, s11);
            s20 = fmaf(qv.z, ka, s20); s21 = fmaf(qv.z, kb, s21);
            s30 = fmaf(qv.w, ka, s30); s31 = fmaf(qv.w, kb, s31);
        }
        Ss[q0 + 0][k0] = s00; Ss[q0 + 0][k0 + 1] = s01;
        Ss[q0 + 1][k0] = s10; Ss[q0 + 1][k0 + 1] = s11;
        Ss[q0 + 2][k0] = s20; Ss[q0 + 2][k0 + 1] = s21;
        Ss[q0 + 3][k0] = s30; Ss[q0 + 3][k0 + 1] = s31;
        __syncthreads();

        // Online softmax: one thread per query row.
        if (tid < 64) {
            int q = tid;
            float mold = m_s[q];
            float mt = mold;
#pragma unroll
            for (int k = 0; k < 32; k++) mt = fmaxf(mt, Ss[q][k]);
            float c = __expf(mold - mt);
            float sum = 0.f;
#pragma unroll
            for (int k = 0; k < 32; k++) {
                float p = __expf(Ss[q][k] - mt);
                Ss[q][k] = p;
                sum += p;
            }
            l_s[q] = l_s[q] * c + sum;
            m_s[q] = mt;
            corr_s[q] = c;
        }
        __syncthreads();

        // O += P @ V: micro 4q x 4d per thread.
        int d0 = tx * 4;
        float c0 = corr_s[q0], c1 = corr_s[q0 + 1], c2 = corr_s[q0 + 2], c3 = corr_s[q0 + 3];
#pragma unroll
        for (int j = 0; j < 4; j++) {
            accO[0][j] *= c0; accO[1][j] *= c1; accO[2][j] *= c2; accO[3][j] *= c3;
        }
#pragma unroll
        for (int k = 0; k < 32; k++) {
            float4 vv = *(const float4*)&Vs[k][d0];
            float p0 = Ss[q0][k], p1 = Ss[q0 + 1][k], p2 = Ss[q0 + 2][k], p3 = Ss[q0 + 3][k];
            accO[0][0] = fmaf(p0, vv.x, accO[0][0]);
            accO[0][1] = fmaf(p0, vv.y, accO[0][1]);
            accO[0][2] = fmaf(p0, vv.z, accO[0][2]);
            accO[0][3] = fmaf(p0, vv.w, accO[0][3]);
            accO[1][0] = fmaf(p1, vv.x, accO[1][0]);
            accO[1][1] = fmaf(p1, vv.y, accO[1][1]);
            accO[1][2] = fmaf(p1, vv.z, accO[1][2]);
            accO[1][3] = fmaf(p1, vv.w, accO[1][3]);
            accO[2][0] = fmaf(p2, vv.x, accO[2][0]);
            accO[2][1] = fmaf(p2, vv.y, accO[2][1]);
            accO[2][2] = fmaf(p2, vv.z, accO[2][2]);
            accO[2][3] = fmaf(p2, vv.w, accO[2][3]);
            accO[3][0] = fmaf(p3, vv.x, accO[3][0]);
            accO[3][1] = fmaf(p3, vv.y, accO[3][1]);
            accO[3][2] = fmaf(p3, vv.z, accO[3][2]);
            accO[3][3] = fmaf(p3, vv.w, accO[3][3]);
        }
    }

    // Final normalize and write: out is [B*S][1024] with col = h*64 + d.
    int d0 = tx * 4;
    float inv0 = 1.f / l_s[q0 + 0];
    float inv1 = 1.f / l_s[q0 + 1];
    float inv2 = 1.f / l_s[q0 + 2];
    float inv3 = 1.f / l_s[q0 + 3];
#pragma unroll
    for (int j = 0; j < 4; j++) {
        size_t col = h * 64 + d0 + j;
        out[(size_t)(b * 2048 + qbase + q0 + 0) * 1024 + col] = accO[0][j] * inv0;
        out[(size_t)(b * 2048 + qbase + q0 + 1) * 1024 + col] = accO[1][j] * inv1;
        out[(size_t)(b * 2048 + qbase + q0 + 2) * 1024 + col] = accO[2][j] * inv2;
        out[(size_t)(b * 2048 + qbase + q0 + 3) * 1024 + col] = accO[3][j] * inv3;
    }
}

extern "C" void kernel_launch(void* const* d_in, const int* in_sizes, int n_in,
                              void* d_out, int out_size)
{
    const float* x     = (const float*)d_in[0];   // [2,2048,1024]
    const float* W_in  = (const float*)d_in[1];   // [3072,1024]
    const float* b_in  = (const float*)d_in[2];   // [3072]
    const float* W_out = (const float*)d_in[3];   // [1024,1024]
    const float* b_out = (const float*)d_in[4];   // [1024]
    float* out = (float*)d_out;                   // [2,2048,1024]

    float* qkv = nullptr;
    float* att = nullptr;
    cudaGetSymbolAddress((void**)&qkv, g_qkv);
    cudaGetSymbolAddress((void**)&att, g_att);

    // 1) QKV projection: [4096,1024] @ [3072,1024]^T + b_in -> [4096,3072]
    gemm_tn_bias<<<dim3(3072 / BN, 4096 / BM), 256>>>(x, W_in, b_in, qkv, 4096, 3072, 1024);
    // 2) Attention: 32 q-tiles x 32 (b,h) pairs
    attn_kernel<<<dim3(32, 32), 256>>>(qkv, att);
    // 3) Output projection: [4096,1024] @ [1024,1024]^T + b_out -> d_out
    gemm_tn_bias<<<dim3(1024 / BN, 4096 / BM), 256>>>(att, W_out, b_out, out, 4096, 1024, 1024);
}

// round 12
// speedup vs baseline: 1.4730x; 1.4730x over previous
#include <cuda_runtime.h>
#include <cuda_bf16.h>
#include <math.h>
#include <stdint.h>

// ===================== scratch (allocation-free) =====================
__device__ float g_qkv[(size_t)4096 * 3072];   // QKV activations fp32
__device__ float g_att[(size_t)4096 * 1024];   // attention output fp32
__device__ __nv_bfloat16 g_xh[(size_t)4096 * 1024], g_xl[(size_t)4096 * 1024];
__device__ __nv_bfloat16 g_wih[(size_t)3072 * 1024], g_wil[(size_t)3072 * 1024];
__device__ __nv_bfloat16 g_woh[(size_t)1024 * 1024], g_wol[(size_t)1024 * 1024];
__device__ __nv_bfloat16 g_ah[(size_t)4096 * 1024], g_al[(size_t)4096 * 1024];

// ===================== baseline-PTX tensor helpers =====================
#define LDSM_X4(r0, r1, r2, r3, addr) \
    asm volatile("ldmatrix.sync.aligned.m8n8.x4.shared.b16 {%0,%1,%2,%3}, [%4];" \
                 : "=r"(r0), "=r"(r1), "=r"(r2), "=r"(r3) : "r"(addr))
#define LDSM_X2(r0, r1, addr) \
    asm volatile("ldmatrix.sync.aligned.m8n8.x2.shared.b16 {%0,%1}, [%2];" \
                 : "=r"(r0), "=r"(r1) : "r"(addr))
#define MMA16816(d, a0, a1, a2, a3, b0, b1) \
    asm volatile("mma.sync.aligned.m16n8k16.row.col.f32.bf16.bf16.f32 " \
                 "{%0,%1,%2,%3}, {%4,%5,%6,%7}, {%8,%9}, {%0,%1,%2,%3};" \
                 : "+f"((d)[0]), "+f"((d)[1]), "+f"((d)[2]), "+f"((d)[3]) \
                 : "r"(a0), "r"(a1), "r"(a2), "r"(a3), "r"(b0), "r"(b1))
#define CP_ASYNC16(saddr, gaddr) \
    asm volatile("cp.async.cg.shared.global [%0], [%1], 16;" :: "r"(saddr), "l"(gaddr))
#define CP_COMMIT() asm volatile("cp.async.commit_group;")
#define CP_WAIT(N) asm volatile("cp.async.wait_group %0;" :: "n"(N))

__device__ __forceinline__ uint32_t smem_to_u32(const void* p) {
    uint32_t a;
    asm("{ .reg .u64 t; cvta.to.shared.u64 t, %1; cvt.u32.u64 %0, t; }" : "=r"(a) : "l"(p));
    return a;
}

// ===================== fp32 -> bf16 hi/lo split =====================
__global__ __launch_bounds__(256) void split_kernel(
    const float* __restrict__ in, __nv_bfloat16* __restrict__ hi,
    __nv_bfloat16* __restrict__ lo, int n4)
{
    int i = blockIdx.x * blockDim.x + threadIdx.x;
    if (i >= n4) return;
    float4 v = ((const float4*)in)[i];
    __nv_bfloat16 h0 = __float2bfloat16(v.x);
    __nv_bfloat16 h1 = __float2bfloat16(v.y);
    __nv_bfloat16 h2 = __float2bfloat16(v.z);
    __nv_bfloat16 h3 = __float2bfloat16(v.w);
    __nv_bfloat162* hp = (__nv_bfloat162*)hi;
    hp[2 * i + 0] = __nv_bfloat162(h0, h1);
    hp[2 * i + 1] = __nv_bfloat162(h2, h3);
    __nv_bfloat162* lp = (__nv_bfloat162*)lo;
    lp[2 * i + 0] = __nv_bfloat162(__float2bfloat16(v.x - __bfloat162float(h0)),
                                   __float2bfloat16(v.y - __bfloat162float(h1)));
    lp[2 * i + 1] = __nv_bfloat162(__float2bfloat16(v.z - __bfloat162float(h2)),
                                   __float2bfloat16(v.w - __bfloat162float(h3)));
}

// ===================== mma.sync split-bf16 GEMM =====================
// C[m,n] = sum_k A[m,k]*B[n,k] + bias[n]  via (Ah+Al)(Bh+Bl), dropping Al*Bl.
// CTA tile 128x128, BK=32, 8 warps (2Mx4N), warp tile 64x32.
// smem per stage: Ah,Al,Bh,Bl each [128][32] bf16, row stride 40 elems (80B).
#define GK 1024
#define GBK 32
#define ROWSTRIDE 40                      // elems; 80 bytes
#define TILE_B (128 * ROWSTRIDE * 2)      // 10240 bytes per tile
#define ST_AH 0
#define ST_AL (TILE_B)
#define ST_BH (2 * TILE_B)
#define ST_BL (3 * TILE_B)
#define STAGE_B (4 * TILE_B)              // 40960
#define GEMM_SMEM (2 * STAGE_B)           // 81920

__global__ __launch_bounds__(256) void gemm_mma_bf16x3(
    const __nv_bfloat16* __restrict__ Ahi, const __nv_bfloat16* __restrict__ Alo,
    const __nv_bfloat16* __restrict__ Bhi, const __nv_bfloat16* __restrict__ Blo,
    const float* __restrict__ bias, float* __restrict__ C, int N)
{
    extern __shared__ char smem[];
    uint32_t sb = smem_to_u32(smem);
    int tid = threadIdx.x;
    int lane = tid & 31;
    int wid = tid >> 5;
    int bm = blockIdx.y * 128, bn = blockIdx.x * 128;
    int warp_m = (wid >> 2) * 64;   // 0 or 64
    int warp_n = (wid & 3) * 32;    // 0,32,64,96

    // per-thread load slots: 512 16B-chunks per array per stage, 2 per thread
    int r0 = tid >> 2, c0 = (tid & 3);            // chunk 0 (rows 0..63)
    int r1 = (tid + 256) >> 2, c1 = tid & 3;      // chunk 1 (rows 64..127)
    const char* gAh = (const char*)Ahi;
    const char* gAl = (const char*)Alo;
    const char* gBh = (const char*)Bhi;
    const char* gBl = (const char*)Blo;

    float acc[4][4][4];
#pragma unroll
    for (int i = 0; i < 4; i++)
#pragma unroll
        for (int j = 0; j < 4; j++)
#pragma unroll
            for (int e = 0; e < 4; e++) acc[i][j][e] = 0.f;

    // fragment address components
    uint32_t a_row = lane & 15;
    uint32_t a_ksel = (lane >> 4) << 3;           // 0 or 8
    uint32_t b_row = lane & 7;
    uint32_t b_ksel = ((lane >> 3) & 1) << 3;     // 0 or 8

    auto issue = [&](int c, int stage) {
        uint32_t s = sb + stage * STAGE_B;
        size_t goA0 = ((size_t)(bm + r0) * GK + c * GBK + c0 * 8) * 2;
        size_t goA1 = ((size_t)(bm + r1) * GK + c * GBK + c1 * 8) * 2;
        size_t goB0 = ((size_t)(bn + r0) * GK + c * GBK + c0 * 8) * 2;
        size_t goB1 = ((size_t)(bn + r1) * GK + c * GBK + c1 * 8) * 2;
        uint32_t so0 = (uint32_t)(r0 * 80 + c0 * 16);
        uint32_t so1 = (uint32_t)(r1 * 80 + c1 * 16);
        CP_ASYNC16(s + ST_AH + so0, gAh + goA0);
        CP_ASYNC16(s + ST_AH + so1, gAh + goA1);
        CP_ASYNC16(s + ST_AL + so0, gAl + goA0);
        CP_ASYNC16(s + ST_AL + so1, gAl + goA1);
        CP_ASYNC16(s + ST_BH + so0, gBh + goB0);
        CP_ASYNC16(s + ST_BH + so1, gBh + goB1);
        CP_ASYNC16(s + ST_BL + so0, gBl + goB0);
        CP_ASYNC16(s + ST_BL + so1, gBl + goB1);
    };

    const int NC = GK / GBK;  // 32
    issue(0, 0);
    CP_COMMIT();

    for (int c = 0; c < NC; c++) {
        int stage = c & 1;
        if (c + 1 < NC) {
            issue(c + 1, stage ^ 1);
            CP_COMMIT();
            CP_WAIT(1);
        } else {
            CP_WAIT(0);
        }
        __syncthreads();

        uint32_t s = sb + stage * STAGE_B;
#pragma unroll
        for (int kk = 0; kk < GBK; kk += 16) {
            uint32_t ah[4][4], al[4][4];
#pragma unroll
            for (int mi = 0; mi < 4; mi++) {
                uint32_t ro = (uint32_t)(warp_m + mi * 16 + a_row) * 80 +
                              (kk + a_ksel) * 2;
                LDSM_X4(ah[mi][0], ah[mi][1], ah[mi][2], ah[mi][3], s + ST_AH + ro);
                LDSM_X4(al[mi][0], al[mi][1], al[mi][2], al[mi][3], s + ST_AL + ro);
            }
            uint32_t bh[4][2], bl[4][2];
#pragma unroll
            for (int ni = 0; ni < 4; ni++) {
                uint32_t ro = (uint32_t)(warp_n + ni * 8 + b_row) * 80 +
                              (kk + b_ksel) * 2;
                LDSM_X2(bh[ni][0], bh[ni][1], s + ST_BH + ro);
                LDSM_X2(bl[ni][0], bl[ni][1], s + ST_BL + ro);
            }
#pragma unroll
            for (int mi = 0; mi < 4; mi++)
#pragma unroll
                for (int ni = 0; ni < 4; ni++) {
                    MMA16816(acc[mi][ni], ah[mi][0], ah[mi][1], ah[mi][2], ah[mi][3],
                             bh[ni][0], bh[ni][1]);
                    MMA16816(acc[mi][ni], ah[mi][0], ah[mi][1], ah[mi][2], ah[mi][3],
                             bl[ni][0], bl[ni][1]);
                    MMA16816(acc[mi][ni], al[mi][0], al[mi][1], al[mi][2], al[mi][3],
                             bh[ni][0], bh[ni][1]);
                }
        }
        __syncthreads();
    }

    // epilogue
#pragma unroll
    for (int mi = 0; mi < 4; mi++) {
        int row = bm + warp_m + mi * 16 + (lane >> 2);
#pragma unroll
        for (int ni = 0; ni < 4; ni++) {
            int col = bn + warp_n + ni * 8 + (lane & 3) * 2;
            float bx = __ldg(&bias[col]), by = __ldg(&bias[col + 1]);
            float2 v0 = make_float2(acc[mi][ni][0] + bx, acc[mi][ni][1] + by);
            float2 v1 = make_float2(acc[mi][ni][2] + bx, acc[mi][ni][3] + by);
            *(float2*)&C[(size_t)row * N + col] = v0;
            *(float2*)&C[(size_t)(row + 8) * N + col] = v1;
        }
    }
}

// ===================== flash attention fp32 (SIMT) =====================
// Block: 128 queries of one (b,h), 256 threads, k-tile 64, micro 8q x 4k / 8q x 4d.
#define ATT_QT 0
#define ATT_KT (64 * 132)
#define ATT_VS (64 * 132 + 64 * 68)
#define ATT_ST (64 * 132 + 2 * 64 * 68)
#define ATT_SMEM ((64 * 132 * 2 + 2 * 64 * 68) * 4)

__global__ __launch_bounds__(256, 2) void attn_kernel(
    const float* __restrict__ qkv, float* __restrict__ out)
{
    extern __shared__ float sm[];
    float* Qt = sm + ATT_QT;
    float* Kt = sm + ATT_KT;
    float* Vs = sm + ATT_VS;
    float* St = sm + ATT_ST;

    int tid = threadIdx.x;
    int ty = tid >> 4, tx = tid & 15;
    int bh = blockIdx.y;
    int b = bh >> 4, h = bh & 15;
    int qbase = blockIdx.x * 128;
    const float* base = qkv + (size_t)b * 2048 * 3072 + h * 64;
    const float scale = 0.125f;

#pragma unroll
    for (int i = 0; i < 8; i++) {
        int idx = i * 256 + tid;
        int q = idx >> 4;
        int d4 = (idx & 15) * 4;
        float4 v = *(const float4*)&base[(size_t)(qbase + q) * 3072 + d4];
        Qt[(d4 + 0) * 132 + q] = v.x * scale;
        Qt[(d4 + 1) * 132 + q] = v.y * scale;
        Qt[(d4 + 2) * 132 + q] = v.z * scale;
        Qt[(d4 + 3) * 132 + q] = v.w * scale;
    }

    int q0 = ty * 8;
    int k0 = tx * 4;
    int d0 = tx * 4;

    float m_run[8], l_run[8];
    float accO[8][4];
#pragma unroll
    for (int i = 0; i < 8; i++) {
        m_run[i] = -INFINITY; l_run[i] = 0.f;
#pragma unroll
        for (int j = 0; j < 4; j++) accO[i][j] = 0.f;
    }

    for (int kt = 0; kt < 2048; kt += 64) {
        __syncthreads();
#pragma unroll
        for (int i = 0; i < 4; i++) {
            int idx = i * 256 + tid;
            int r = idx >> 4;
            int d4 = (idx & 15) * 4;
            const float* rp = &base[(size_t)(kt + r) * 3072 + d4];
            float4 kv = *(const float4*)(rp + 1024);
            Kt[(d4 + 0) * 68 + r] = kv.x;
            Kt[(d4 + 1) * 68 + r] = kv.y;
            Kt[(d4 + 2) * 68 + r] = kv.z;
            Kt[(d4 + 3) * 68 + r] = kv.w;
            *(float4*)&Vs[r * 68 + d4] = *(const float4*)(rp + 2048);
        }
        __syncthreads();

        float s[8][4];
#pragma unroll
        for (int i = 0; i < 8; i++)
#pragma unroll
            for (int j = 0; j < 4; j++) s[i][j] = 0.f;
#pragma unroll
        for (int dd = 0; dd < 64; dd++) {
            float4 qa = *(const float4*)&Qt[dd * 132 + q0];
            float4 qb = *(const float4*)&Qt[dd * 132 + q0 + 4];
            float4 kv = *(const float4*)&Kt[dd * 68 + k0];
            float qr[8] = {qa.x, qa.y, qa.z, qa.w, qb.x, qb.y, qb.z, qb.w};
            float kr[4] = {kv.x, kv.y, kv.z, kv.w};
#pragma unroll
            for (int i = 0; i < 8; i++)
#pragma unroll
                for (int j = 0; j < 4; j++)
                    s[i][j] = fmaf(qr[i], kr[j], s[i][j]);
        }

        float cvec[8];
#pragma unroll
        for (int i = 0; i < 8; i++) {
            float tmax = fmaxf(fmaxf(s[i][0], s[i][1]), fmaxf(s[i][2], s[i][3]));
            tmax = fmaxf(tmax, __shfl_xor_sync(0xffffffffu, tmax, 1));
            tmax = fmaxf(tmax, __shfl_xor_sync(0xffffffffu, tmax, 2));
            tmax = fmaxf(tmax, __shfl_xor_sync(0xffffffffu, tmax, 4));
            tmax = fmaxf(tmax, __shfl_xor_sync(0xffffffffu, tmax, 8));
            float mt = fmaxf(m_run[i], tmax);
            float c = __expf(m_run[i] - mt);
            float rs = 0.f;
#pragma unroll
            for (int j = 0; j < 4; j++) {
                s[i][j] = __expf(s[i][j] - mt);
                rs += s[i][j];
            }
            rs += __shfl_xor_sync(0xffffffffu, rs, 1);
            rs += __shfl_xor_sync(0xffffffffu, rs, 2);
            rs += __shfl_xor_sync(0xffffffffu, rs, 4);
            rs += __shfl_xor_sync(0xffffffffu, rs, 8);
            l_run[i] = l_run[i] * c + rs;
            m_run[i] = mt;
            cvec[i] = c;
        }

#pragma unroll
        for (int j = 0; j < 4; j++) {
            float4 a = make_float4(s[0][j], s[1][j], s[2][j], s[3][j]);
            float4 bq = make_float4(s[4][j], s[5][j], s[6][j], s[7][j]);
            *(float4*)&St[(k0 + j) * 132 + q0] = a;
            *(float4*)&St[(k0 + j) * 132 + q0 + 4] = bq;
        }
        __syncthreads();

#pragma unroll
        for (int i = 0; i < 8; i++)
#pragma unroll
            for (int j = 0; j < 4; j++) accO[i][j] *= cvec[i];
#pragma unroll
        for (int k = 0; k < 64; k++) {
            float4 pa = *(const float4*)&St[k * 132 + q0];
            float4 pb = *(const float4*)&St[k * 132 + q0 + 4];
            float4 vv = *(const float4*)&Vs[k * 68 + d0];
            float pr[8] = {pa.x, pa.y, pa.z, pa.w, pb.x, pb.y, pb.z, pb.w};
#pragma unroll
            for (int i = 0; i < 8; i++) {
                accO[i][0] = fmaf(pr[i], vv.x, accO[i][0]);
                accO[i][1] = fmaf(pr[i], vv.y, accO[i][1]);
                accO[i][2] = fmaf(pr[i], vv.z, accO[i][2]);
                accO[i][3] = fmaf(pr[i], vv.w, accO[i][3]);
            }
        }
    }

#pragma unroll
    for (int i = 0; i < 8; i++) {
        float inv = 1.f / l_run[i];
        size_t row = (size_t)(b * 2048 + qbase + q0 + i);
        float4 v = make_float4(accO[i][0] * inv, accO[i][1] * inv,
                               accO[i][2] * inv, accO[i][3] * inv);
        *(float4*)&out[row * 1024 + h * 64 + d0] = v;
    }
}

// ===================== launch =====================
extern "C" void kernel_launch(void* const* d_in, const int* in_sizes, int n_in,
                              void* d_out, int out_size)
{
    const float* x     = (const float*)d_in[0];   // [2,2048,1024]
    const float* W_in  = (const float*)d_in[1];   // [3072,1024]
    const float* b_in  = (const float*)d_in[2];   // [3072]
    const float* W_out = (const float*)d_in[3];   // [1024,1024]
    const float* b_out = (const float*)d_in[4];   // [1024]
    float* out = (float*)d_out;

    float *qkv, *att;
    __nv_bfloat16 *xh, *xl, *wih, *wil, *woh, *wol, *ah, *al;
    cudaGetSymbolAddress((void**)&qkv, g_qkv);
    cudaGetSymbolAddress((void**)&att, g_att);
    cudaGetSymbolAddress((void**)&xh, g_xh);
    cudaGetSymbolAddress((void**)&xl, g_xl);
    cudaGetSymbolAddress((void**)&wih, g_wih);
    cudaGetSymbolAddress((void**)&wil, g_wil);
    cudaGetSymbolAddress((void**)&woh, g_woh);
    cudaGetSymbolAddress((void**)&wol, g_wol);
    cudaGetSymbolAddress((void**)&ah, g_ah);
    cudaGetSymbolAddress((void**)&al, g_al);

    cudaFuncSetAttribute(gemm_mma_bf16x3, cudaFuncAttributeMaxDynamicSharedMemorySize, GEMM_SMEM);
    cudaFuncSetAttribute(attn_kernel, cudaFuncAttributeMaxDynamicSharedMemorySize, ATT_SMEM);

    // split inputs to bf16 hi/lo
    split_kernel<<<4096, 256>>>(x, xh, xl, 4096 * 1024 / 4);
    split_kernel<<<3072, 256>>>(W_in, wih, wil, 3072 * 1024 / 4);
    split_kernel<<<1024, 256>>>(W_out, woh, wol, 1024 * 1024 / 4);

    // 1) QKV projection: [4096,1024] @ [3072,1024]^T + b_in
    gemm_mma_bf16x3<<<dim3(3072 / 128, 4096 / 128), 256, GEMM_SMEM>>>(
        xh, xl, wih, wil, b_in, qkv, 3072);

    // 2) attention
    attn_kernel<<<dim3(2048 / 128, 32), 256, ATT_SMEM>>>(qkv, att);

    // 3) output projection
    split_kernel<<<4096, 256>>>(att, ah, al, 4096 * 1024 / 4);
    gemm_mma_bf16x3<<<dim3(1024 / 128, 4096 / 128), 256, GEMM_SMEM>>>(
        ah, al, woh, wol, b_out, out, 1024);
}